// round 7
// baseline (speedup 1.0000x reference)
#include <cuda_runtime.h>
#include <cuda_bf16.h>
#include <math.h>

// Problem constants
#define CB   8
#define CS   4096
#define CD   512
#define CP   128
#define CL   4
#define CDF  2048
#define CDH  256
#define CC   2
#define CBS  (CB*CS)          // 32768 tokens

#define KVSPLIT 8
#define PKCH    32
#define POOLCH  16

// ---------------- scratch (device globals; no allocation allowed) ----------------
__device__ float g_h   [(size_t)CBS*CD];
__device__ float g_q   [(size_t)CBS*CD];
__device__ float g_k   [(size_t)CBS*CD];
__device__ float g_v   [(size_t)CBS*CD];
__device__ float g_a   [(size_t)CBS*CD];
__device__ float g_pq  [(size_t)CBS*CP];
__device__ float g_pk  [(size_t)CBS*CP];
__device__ float g_mlp [(size_t)CBS*CDF];
__device__ float g_kv  [(size_t)CB*CP*CD];
__device__ float g_kvp [(size_t)CB*KVSPLIT*CP*CD];
__device__ float g_pks [(size_t)CB*CP];
__device__ float g_pkp [(size_t)PKCH*CB*CP];
__device__ float g_z   [(size_t)CBS];
__device__ float g_pool[(size_t)CB*CD];
__device__ float g_poolp[(size_t)POOLCH*CB*CD];
__device__ float g_h1  [(size_t)CB*CDH];

// ---------------- embedding ----------------
__global__ void embed_kernel(const int* __restrict__ x,
                             const float* __restrict__ emb,
                             const float* __restrict__ pos)
{
    long row = blockIdx.x;                // 0..CBS-1
    int  s   = (int)(row & (CS - 1));
    int  tok = x[row];
    int  t   = threadIdx.x;               // 128 threads, float4 each
    float4 e = ((const float4*)(emb + (long)tok * CD))[t];
    float4 p = ((const float4*)(pos + (long)s   * CD))[t];
    ((float4*)(g_h + row * CD))[t] = make_float4(e.x+p.x, e.y+p.y, e.z+p.z, e.w+p.w);
}

// ---------------- generic NN SGEMM, 128x128x8, epilogues ----------------
// EPI: 0 = +bias ; 1 = elu(+bias)+1 ; 2 = tanh-gelu(+bias) ; 3 = /(z+1e-6), no bias
template<int EPI>
__global__ __launch_bounds__(256)
void sgemm_nn(const float* __restrict__ A, const float* __restrict__ W,
              const float* __restrict__ bias, float* __restrict__ Cc,
              int M, int N, int K,
              long sA, long sB, long sC,
              const float* __restrict__ zvec)
{
    const int bz = blockIdx.z;
    A  += (long)bz * sA;
    W  += (long)bz * sB;
    Cc += (long)bz * sC;

    __shared__ float As[8][128];
    __shared__ float Bs[8][128];

    const int tid  = threadIdx.x;
    const int brow = blockIdx.y * 128;
    const int bcol = blockIdx.x * 128;

    const int aRow = tid >> 1;
    const int aCol = (tid & 1) << 2;
    const int bRow = tid >> 5;
    const int bCol = (tid & 31) << 2;

    const int mBase = (tid >> 4) << 3;
    const int nBase = (tid & 15) << 3;

    float acc[8][8];
    #pragma unroll
    for (int i = 0; i < 8; i++)
        #pragma unroll
        for (int j = 0; j < 8; j++) acc[i][j] = 0.f;

    const float* Ap = A + (long)(brow + aRow) * K + aCol;
    const float* Bp = W + (long)bRow * N + bcol + bCol;

    for (int k0 = 0; k0 < K; k0 += 8) {
        float4 av = *(const float4*)(Ap + k0);
        As[aCol+0][aRow] = av.x;
        As[aCol+1][aRow] = av.y;
        As[aCol+2][aRow] = av.z;
        As[aCol+3][aRow] = av.w;
        float4 bv = *(const float4*)(Bp + (long)k0 * N);
        *(float4*)&Bs[bRow][bCol] = bv;
        __syncthreads();
        #pragma unroll
        for (int k = 0; k < 8; k++) {
            float4 a0 = *(const float4*)&As[k][mBase];
            float4 a1 = *(const float4*)&As[k][mBase+4];
            float4 b0 = *(const float4*)&Bs[k][nBase];
            float4 b1 = *(const float4*)&Bs[k][nBase+4];
            float ra[8] = {a0.x,a0.y,a0.z,a0.w,a1.x,a1.y,a1.z,a1.w};
            float rb[8] = {b0.x,b0.y,b0.z,b0.w,b1.x,b1.y,b1.z,b1.w};
            #pragma unroll
            for (int i = 0; i < 8; i++)
                #pragma unroll
                for (int j = 0; j < 8; j++)
                    acc[i][j] = fmaf(ra[i], rb[j], acc[i][j]);
        }
        __syncthreads();
    }

    float bvals[8];
    #pragma unroll
    for (int j = 0; j < 8; j++)
        bvals[j] = (EPI == 3) ? 0.f : bias[bcol + nBase + j];

    #pragma unroll
    for (int i = 0; i < 8; i++) {
        const int m = brow + mBase + i;
        float zin = 1.f;
        if (EPI == 3) zin = 1.f / (zvec[(long)bz * CS + m] + 1e-6f);
        float outv[8];
        #pragma unroll
        for (int j = 0; j < 8; j++) {
            float v = acc[i][j] + bvals[j];
            if (EPI == 1) {
                v = (v > 0.f) ? (v + 1.f) : expf(v);
            } else if (EPI == 2) {
                float u = 0.7978845608028654f * (v + 0.044715f * v * v * v);
                v = 0.5f * v * (1.f + tanhf(u));
            } else if (EPI == 3) {
                v = v * zin;
            }
            outv[j] = v;
        }
        float4* cp = (float4*)(Cc + (long)m * N + bcol + nBase);
        cp[0] = make_float4(outv[0], outv[1], outv[2], outv[3]);
        cp[1] = make_float4(outv[4], outv[5], outv[6], outv[7]);
    }
}

// ---------------- TN SGEMM for kv = pk^T @ v, deterministic split-K ----------------
// C_part[b*KVSPLIT+split][p][d] = sum_{s in chunk} pk[b][s][p] * v[b][s][d]
__global__ __launch_bounds__(256)
void sgemm_tn_split(void)
{
    const int bz    = blockIdx.z;          // b*KVSPLIT + split
    const int b     = bz / KVSPLIT;
    const int split = bz % KVSPLIT;
    const int kBeg  = split * (CS / KVSPLIT);

    const float* A  = g_pk + (long)b * CS * CP;   // [S][P]
    const float* Bm = g_v  + (long)b * CS * CD;   // [S][D]
    float*       Cc = g_kvp + (long)bz * CP * CD;

    const int tid  = threadIdx.x;
    const int bcol = blockIdx.x * 128;     // within D

    __shared__ float As[8][128];
    __shared__ float Bs[8][128];

    const int lRow = tid >> 5;             // k in tile (0..7)
    const int lCol = (tid & 31) << 2;

    const int mBase = (tid >> 4) << 3;
    const int nBase = (tid & 15) << 3;

    float acc[8][8];
    #pragma unroll
    for (int i = 0; i < 8; i++)
        #pragma unroll
        for (int j = 0; j < 8; j++) acc[i][j] = 0.f;

    for (int k0 = 0; k0 < CS / KVSPLIT; k0 += 8) {
        const long kk = kBeg + k0 + lRow;
        *(float4*)&As[lRow][lCol] = *(const float4*)(A  + kk * CP + lCol);
        *(float4*)&Bs[lRow][lCol] = *(const float4*)(Bm + kk * CD + bcol + lCol);
        __syncthreads();
        #pragma unroll
        for (int k = 0; k < 8; k++) {
            float4 a0 = *(const float4*)&As[k][mBase];
            float4 a1 = *(const float4*)&As[k][mBase+4];
            float4 b0 = *(const float4*)&Bs[k][nBase];
            float4 b1 = *(const float4*)&Bs[k][nBase+4];
            float ra[8] = {a0.x,a0.y,a0.z,a0.w,a1.x,a1.y,a1.z,a1.w};
            float rb[8] = {b0.x,b0.y,b0.z,b0.w,b1.x,b1.y,b1.z,b1.w};
            #pragma unroll
            for (int i = 0; i < 8; i++)
                #pragma unroll
                for (int j = 0; j < 8; j++)
                    acc[i][j] = fmaf(ra[i], rb[j], acc[i][j]);
        }
        __syncthreads();
    }

    #pragma unroll
    for (int i = 0; i < 8; i++) {
        float4* cp = (float4*)(Cc + (long)(mBase + i) * CD + bcol + nBase);
        cp[0] = make_float4(acc[i][0], acc[i][1], acc[i][2], acc[i][3]);
        cp[1] = make_float4(acc[i][4], acc[i][5], acc[i][6], acc[i][7]);
    }
}

__global__ void kv_reduce_kernel(void)
{
    long idx = (long)blockIdx.x * blockDim.x + threadIdx.x;   // over CB*CP*CD
    if (idx >= (long)CB * CP * CD) return;
    long b = idx / (CP * CD);
    long r = idx % (CP * CD);
    float s = 0.f;
    #pragma unroll
    for (int sp = 0; sp < KVSPLIT; sp++)
        s += g_kvp[(b * KVSPLIT + sp) * (long)(CP * CD) + r];
    g_kv[idx] = s;
}

// ---------------- pk.sum over S ----------------
__global__ void pksum_part_kernel(void)   // grid (CB, PKCH), block 128
{
    int b = blockIdx.x, ch = blockIdx.y, t = threadIdx.x;
    const int chunk = CS / PKCH;
    float acc = 0.f;
    const float* p = g_pk + ((long)b * CS + (long)ch * chunk) * CP + t;
    for (int s = 0; s < chunk; s++) acc += p[(long)s * CP];
    g_pkp[((long)ch * CB + b) * CP + t] = acc;
}

__global__ void pksum_reduce_kernel(void)
{
    int idx = blockIdx.x * blockDim.x + threadIdx.x;
    if (idx >= CB * CP) return;
    float s = 0.f;
    #pragma unroll
    for (int ch = 0; ch < PKCH; ch++)
        s += g_pkp[(long)ch * CB * CP + idx];
    g_pks[idx] = s;
}

// ---------------- z = pq . pksum (per row) ----------------
__global__ void z_kernel(void)   // grid CBS/8, block 256 (8 warps)
{
    const long row  = (long)blockIdx.x * 8 + (threadIdx.x >> 5);
    const int  lane = threadIdx.x & 31;
    const int  b    = (int)(row / CS);
    const float* pr = g_pq  + row * CP;
    const float* ps = g_pks + (long)b * CP;
    float acc = 0.f;
    #pragma unroll
    for (int i = lane; i < CP; i += 32) acc += pr[i] * ps[i];
    #pragma unroll
    for (int o = 16; o; o >>= 1) acc += __shfl_xor_sync(0xffffffffu, acc, o);
    if (lane == 0) g_z[row] = acc;
}

// ---------------- layernorm, in-place, one 128-thread block per row ----------------
__global__ void ln_kernel(float* __restrict__ X,
                          const float* __restrict__ gamma,
                          const float* __restrict__ beta)
{
    __shared__ float red[128];
    const long row = blockIdx.x;
    float4* xp = (float4*)(X + row * CD);
    const int t = threadIdx.x;
    float4 v = xp[t];

    red[t] = v.x + v.y + v.z + v.w;
    __syncthreads();
    for (int o = 64; o; o >>= 1) { if (t < o) red[t] += red[t + o]; __syncthreads(); }
    const float mu = red[0] * (1.f / CD);
    __syncthreads();

    float dx = v.x - mu, dy = v.y - mu, dz = v.z - mu, dw = v.w - mu;
    red[t] = dx*dx + dy*dy + dz*dz + dw*dw;
    __syncthreads();
    for (int o = 64; o; o >>= 1) { if (t < o) red[t] += red[t + o]; __syncthreads(); }
    const float rstd = rsqrtf(red[0] * (1.f / CD) + 1e-5f);

    const float4 g4 = ((const float4*)gamma)[t];
    const float4 b4 = ((const float4*)beta)[t];
    float4 o;
    o.x = dx * rstd * g4.x + b4.x;
    o.y = dy * rstd * g4.y + b4.y;
    o.z = dz * rstd * g4.z + b4.z;
    o.w = dw * rstd * g4.w + b4.w;
    xp[t] = o;
}

// ---------------- mean pool over S ----------------
__global__ void pool_part_kernel(void)    // grid (CB, POOLCH), block CD
{
    int b = blockIdx.x, ch = blockIdx.y, d = threadIdx.x;
    const int chunk = CS / POOLCH;
    float acc = 0.f;
    const float* p = g_h + ((long)b * CS + (long)ch * chunk) * CD + d;
    for (int s = 0; s < chunk; s++) acc += p[(long)s * CD];
    g_poolp[((long)ch * CB + b) * CD + d] = acc;
}

__global__ void pool_reduce_kernel(void)
{
    int idx = blockIdx.x * blockDim.x + threadIdx.x;
    if (idx >= CB * CD) return;
    float s = 0.f;
    #pragma unroll
    for (int ch = 0; ch < POOLCH; ch++)
        s += g_poolp[(long)ch * CB * CD + idx];
    g_pool[idx] = s * (1.f / CS);
}

// ---------------- head ----------------
__global__ void head1_kernel(const float* __restrict__ Wh1,
                             const float* __restrict__ bh1)
{
    int b = blockIdx.x, t = threadIdx.x;       // block = CDH threads
    const float* pr = g_pool + (long)b * CD;
    float acc = 0.f;
    for (int k = 0; k < CD; k++)
        acc = fmaf(pr[k], Wh1[(long)k * CDH + t], acc);
    float v = acc + bh1[t];
    g_h1[(long)b * CDH + t] = v > 0.f ? v : 0.f;
}

__global__ void head2_kernel(const float* __restrict__ Wh2,
                             const float* __restrict__ bh2,
                             float* __restrict__ out)
{
    int idx = threadIdx.x;
    if (idx >= CB * CC) return;
    int b = idx / CC, c = idx % CC;
    const float* h1 = g_h1 + (long)b * CDH;
    float acc = 0.f;
    for (int k = 0; k < CDH; k++)
        acc = fmaf(h1[k], Wh2[(long)k * CC + c], acc);
    out[idx] = acc + bh2[c];
}

// ---------------- host ----------------
extern "C" void kernel_launch(void* const* d_in, const int* in_sizes, int n_in,
                              void* d_out, int out_size)
{
    (void)in_sizes; (void)n_in; (void)out_size;

    const int*   x    = (const int*)  d_in[0];
    const float* emb  = (const float*)d_in[1];
    const float* pos  = (const float*)d_in[2];
    const float* Wq   = (const float*)d_in[3];
    const float* bq   = (const float*)d_in[4];
    const float* Wk   = (const float*)d_in[5];
    const float* bk   = (const float*)d_in[6];
    const float* Wv   = (const float*)d_in[7];
    const float* bv   = (const float*)d_in[8];
    const float* Wf   = (const float*)d_in[9];
    const float* bf   = (const float*)d_in[10];
    const float* Wo   = (const float*)d_in[11];
    const float* bo   = (const float*)d_in[12];
    const float* lng  = (const float*)d_in[13];
    const float* lnb  = (const float*)d_in[14];
    const float* W1   = (const float*)d_in[15];
    const float* b1   = (const float*)d_in[16];
    const float* W2   = (const float*)d_in[17];
    const float* b2   = (const float*)d_in[18];
    const float* Wh1  = (const float*)d_in[19];
    const float* bh1  = (const float*)d_in[20];
    const float* Wh2  = (const float*)d_in[21];
    const float* bh2  = (const float*)d_in[22];
    float* out = (float*)d_out;

    float *ph, *pq, *pk, *pv, *pa, *ppq, *ppk, *pmlp, *pkv, *pz;
    cudaGetSymbolAddress((void**)&ph,   g_h);
    cudaGetSymbolAddress((void**)&pq,   g_q);
    cudaGetSymbolAddress((void**)&pk,   g_k);
    cudaGetSymbolAddress((void**)&pv,   g_v);
    cudaGetSymbolAddress((void**)&pa,   g_a);
    cudaGetSymbolAddress((void**)&ppq,  g_pq);
    cudaGetSymbolAddress((void**)&ppk,  g_pk);
    cudaGetSymbolAddress((void**)&pmlp, g_mlp);
    cudaGetSymbolAddress((void**)&pkv,  g_kv);
    cudaGetSymbolAddress((void**)&pz,   g_z);

    embed_kernel<<<CBS, 128>>>(x, emb, pos);

    for (int l = 0; l < CL; l++) {
        const float* wq = Wq + (long)l * CD * CD;
        const float* wk = Wk + (long)l * CD * CD;
        const float* wv = Wv + (long)l * CD * CD;
        const float* wf = Wf + (long)l * CD * CP;
        const float* wo = Wo + (long)l * CD * CD;
        const float* w1 = W1 + (long)l * CD * CDF;
        const float* w2 = W2 + (long)l * CDF * CD;
        const float* biq = bq + (long)l * CD;
        const float* bik = bk + (long)l * CD;
        const float* biv = bv + (long)l * CD;
        const float* bif = bf + (long)l * CP;
        const float* bio = bo + (long)l * CD;
        const float* bi1 = b1 + (long)l * CDF;
        const float* bi2 = b2 + (long)l * CD;

        dim3 gQKV(CD / 128, CBS / 128, 1);
        sgemm_nn<0><<<gQKV, 256>>>(ph, wq, biq, pq, CBS, CD, CD, 0, 0, 0, nullptr);
        sgemm_nn<0><<<gQKV, 256>>>(ph, wk, bik, pk, CBS, CD, CD, 0, 0, 0, nullptr);
        sgemm_nn<0><<<gQKV, 256>>>(ph, wv, biv, pv, CBS, CD, CD, 0, 0, 0, nullptr);

        dim3 gF(CP / 128, CBS / 128, 1);
        sgemm_nn<1><<<gF, 256>>>(pq, wf, bif, ppq, CBS, CP, CD, 0, 0, 0, nullptr);
        sgemm_nn<1><<<gF, 256>>>(pk, wf, bif, ppk, CBS, CP, CD, 0, 0, 0, nullptr);

        pksum_part_kernel<<<dim3(CB, PKCH), 128>>>();
        pksum_reduce_kernel<<<(CB * CP + 255) / 256, 256>>>();

        sgemm_tn_split<<<dim3(CD / 128, 1, CB * KVSPLIT), 256>>>();
        kv_reduce_kernel<<<(CB * CP * CD + 255) / 256, 256>>>();

        z_kernel<<<CBS / 8, 256>>>();

        // out[b,s,d] = (pq @ kv) / (z + eps)   (batched)
        dim3 gO(CD / 128, CS / 128, CB);
        sgemm_nn<3><<<gO, 256>>>(ppq, pkv, nullptr, pa,
                                 CS, CD, CP,
                                 (long)CS * CP, (long)CP * CD, (long)CS * CD, pz);

        sgemm_nn<0><<<gQKV, 256>>>(pa, wo, bio, pq, CBS, CD, CD, 0, 0, 0, nullptr);

        ln_kernel<<<CBS, 128>>>(pq, lng + (long)l * CD, lnb + (long)l * CD);

        dim3 g1(CDF / 128, CBS / 128, 1);
        sgemm_nn<2><<<g1, 256>>>(pq, w1, bi1, pmlp, CBS, CDF, CD, 0, 0, 0, nullptr);

        dim3 g2(CD / 128, CBS / 128, 1);
        sgemm_nn<0><<<g2, 256>>>(pmlp, w2, bi2, ph, CBS, CD, CDF, 0, 0, 0, nullptr);
    }

    pool_part_kernel<<<dim3(CB, POOLCH), CD>>>();
    pool_reduce_kernel<<<(CB * CD + 255) / 256, 256>>>();
    head1_kernel<<<CB, CDH>>>(Wh1, bh1);
    head2_kernel<<<1, 32>>>(Wh2, bh2, out);
}

// round 8
// speedup vs baseline: 1.0010x; 1.0010x over previous
#include <cuda_runtime.h>
#include <cuda_bf16.h>
#include <math.h>

// Problem constants
#define CB   8
#define CS   4096
#define CD   512
#define CP   128
#define CL   4
#define CDF  2048
#define CDH  256
#define CC   2
#define CBS  (CB*CS)          // 32768 tokens

#define KVSPLIT 8
#define PKCH    32
#define POOLCH  16

// ---------------- scratch (device globals; no allocation allowed) ----------------
__device__ float g_h   [(size_t)CBS*CD];
__device__ float g_q   [(size_t)CBS*CD];
__device__ float g_k   [(size_t)CBS*CD];
__device__ float g_v   [(size_t)CBS*CD];
__device__ float g_a   [(size_t)CBS*CD];
__device__ float g_pq  [(size_t)CBS*CP];
__device__ float g_pk  [(size_t)CBS*CP];
__device__ float g_mlp [(size_t)CBS*CDF];
__device__ float g_kv  [(size_t)CB*CP*CD];
__device__ float g_kvp [(size_t)CB*KVSPLIT*CP*CD];
__device__ float g_pks [(size_t)CB*CP];
__device__ float g_pkp [(size_t)PKCH*CB*CP];
__device__ float g_z   [(size_t)CBS];
__device__ float g_pool[(size_t)CB*CD];
__device__ float g_poolp[(size_t)POOLCH*CB*CD];
__device__ float g_h1  [(size_t)CB*CDH];

// ---------------- embedding ----------------
__global__ void embed_kernel(const int* __restrict__ x,
                             const float* __restrict__ emb,
                             const float* __restrict__ pos)
{
    long row = blockIdx.x;                // 0..CBS-1
    int  s   = (int)(row & (CS - 1));
    int  tok = x[row];
    int  t   = threadIdx.x;               // 128 threads, float4 each
    float4 e = ((const float4*)(emb + (long)tok * CD))[t];
    float4 p = ((const float4*)(pos + (long)s   * CD))[t];
    ((float4*)(g_h + row * CD))[t] = make_float4(e.x+p.x, e.y+p.y, e.z+p.z, e.w+p.w);
}

// ---------------- generic NN SGEMM, 128x128x8, epilogues ----------------
// EPI: 0 = +bias ; 1 = elu(+bias)+1 ; 2 = tanh-gelu(+bias) ; 3 = /(z+1e-6), no bias
template<int EPI>
__global__ __launch_bounds__(256)
void sgemm_nn(const float* __restrict__ A, const float* __restrict__ W,
              const float* __restrict__ bias, float* __restrict__ Cc,
              int M, int N, int K,
              long sA, long sB, long sC,
              const float* __restrict__ zvec)
{
    const int bz = blockIdx.z;
    A  += (long)bz * sA;
    W  += (long)bz * sB;
    Cc += (long)bz * sC;

    __shared__ float As[8][128];
    __shared__ float Bs[8][128];

    const int tid  = threadIdx.x;
    const int brow = blockIdx.y * 128;
    const int bcol = blockIdx.x * 128;

    const int aRow = tid >> 1;
    const int aCol = (tid & 1) << 2;
    const int bRow = tid >> 5;
    const int bCol = (tid & 31) << 2;

    const int mBase = (tid >> 4) << 3;
    const int nBase = (tid & 15) << 3;

    float acc[8][8];
    #pragma unroll
    for (int i = 0; i < 8; i++)
        #pragma unroll
        for (int j = 0; j < 8; j++) acc[i][j] = 0.f;

    const float* Ap = A + (long)(brow + aRow) * K + aCol;
    const float* Bp = W + (long)bRow * N + bcol + bCol;

    for (int k0 = 0; k0 < K; k0 += 8) {
        float4 av = *(const float4*)(Ap + k0);
        As[aCol+0][aRow] = av.x;
        As[aCol+1][aRow] = av.y;
        As[aCol+2][aRow] = av.z;
        As[aCol+3][aRow] = av.w;
        float4 bv = *(const float4*)(Bp + (long)k0 * N);
        *(float4*)&Bs[bRow][bCol] = bv;
        __syncthreads();
        #pragma unroll
        for (int k = 0; k < 8; k++) {
            float4 a0 = *(const float4*)&As[k][mBase];
            float4 a1 = *(const float4*)&As[k][mBase+4];
            float4 b0 = *(const float4*)&Bs[k][nBase];
            float4 b1 = *(const float4*)&Bs[k][nBase+4];
            float ra[8] = {a0.x,a0.y,a0.z,a0.w,a1.x,a1.y,a1.z,a1.w};
            float rb[8] = {b0.x,b0.y,b0.z,b0.w,b1.x,b1.y,b1.z,b1.w};
            #pragma unroll
            for (int i = 0; i < 8; i++)
                #pragma unroll
                for (int j = 0; j < 8; j++)
                    acc[i][j] = fmaf(ra[i], rb[j], acc[i][j]);
        }
        __syncthreads();
    }

    float bvals[8];
    #pragma unroll
    for (int j = 0; j < 8; j++)
        bvals[j] = (EPI == 3) ? 0.f : bias[bcol + nBase + j];

    #pragma unroll
    for (int i = 0; i < 8; i++) {
        const int m = brow + mBase + i;
        float zin = 1.f;
        if (EPI == 3) zin = 1.f / (zvec[(long)bz * CS + m] + 1e-6f);
        float outv[8];
        #pragma unroll
        for (int j = 0; j < 8; j++) {
            float v = acc[i][j] + bvals[j];
            if (EPI == 1) {
                v = (v > 0.f) ? (v + 1.f) : expf(v);
            } else if (EPI == 2) {
                float u = 0.7978845608028654f * (v + 0.044715f * v * v * v);
                v = 0.5f * v * (1.f + tanhf(u));
            } else if (EPI == 3) {
                v = v * zin;
            }
            outv[j] = v;
        }
        float4* cp = (float4*)(Cc + (long)m * N + bcol + nBase);
        cp[0] = make_float4(outv[0], outv[1], outv[2], outv[3]);
        cp[1] = make_float4(outv[4], outv[5], outv[6], outv[7]);
    }
}

// ---------------- TN SGEMM for kv = pk^T @ v, deterministic split-K ----------------
// C_part[b*KVSPLIT+split][p][d] = sum_{s in chunk} pk[b][s][p] * v[b][s][d]
__global__ __launch_bounds__(256)
void sgemm_tn_split(void)
{
    const int bz    = blockIdx.z;          // b*KVSPLIT + split
    const int b     = bz / KVSPLIT;
    const int split = bz % KVSPLIT;
    const int kBeg  = split * (CS / KVSPLIT);

    const float* A  = g_pk + (long)b * CS * CP;   // [S][P]
    const float* Bm = g_v  + (long)b * CS * CD;   // [S][D]
    float*       Cc = g_kvp + (long)bz * CP * CD;

    const int tid  = threadIdx.x;
    const int bcol = blockIdx.x * 128;     // within D

    __shared__ float As[8][128];
    __shared__ float Bs[8][128];

    const int lRow = tid >> 5;             // k in tile (0..7)
    const int lCol = (tid & 31) << 2;

    const int mBase = (tid >> 4) << 3;
    const int nBase = (tid & 15) << 3;

    float acc[8][8];
    #pragma unroll
    for (int i = 0; i < 8; i++)
        #pragma unroll
        for (int j = 0; j < 8; j++) acc[i][j] = 0.f;

    for (int k0 = 0; k0 < CS / KVSPLIT; k0 += 8) {
        const long kk = kBeg + k0 + lRow;
        *(float4*)&As[lRow][lCol] = *(const float4*)(A  + kk * CP + lCol);
        *(float4*)&Bs[lRow][lCol] = *(const float4*)(Bm + kk * CD + bcol + lCol);
        __syncthreads();
        #pragma unroll
        for (int k = 0; k < 8; k++) {
            float4 a0 = *(const float4*)&As[k][mBase];
            float4 a1 = *(const float4*)&As[k][mBase+4];
            float4 b0 = *(const float4*)&Bs[k][nBase];
            float4 b1 = *(const float4*)&Bs[k][nBase+4];
            float ra[8] = {a0.x,a0.y,a0.z,a0.w,a1.x,a1.y,a1.z,a1.w};
            float rb[8] = {b0.x,b0.y,b0.z,b0.w,b1.x,b1.y,b1.z,b1.w};
            #pragma unroll
            for (int i = 0; i < 8; i++)
                #pragma unroll
                for (int j = 0; j < 8; j++)
                    acc[i][j] = fmaf(ra[i], rb[j], acc[i][j]);
        }
        __syncthreads();
    }

    #pragma unroll
    for (int i = 0; i < 8; i++) {
        float4* cp = (float4*)(Cc + (long)(mBase + i) * CD + bcol + nBase);
        cp[0] = make_float4(acc[i][0], acc[i][1], acc[i][2], acc[i][3]);
        cp[1] = make_float4(acc[i][4], acc[i][5], acc[i][6], acc[i][7]);
    }
}

__global__ void kv_reduce_kernel(void)
{
    long idx = (long)blockIdx.x * blockDim.x + threadIdx.x;   // over CB*CP*CD
    if (idx >= (long)CB * CP * CD) return;
    long b = idx / (CP * CD);
    long r = idx % (CP * CD);
    float s = 0.f;
    #pragma unroll
    for (int sp = 0; sp < KVSPLIT; sp++)
        s += g_kvp[(b * KVSPLIT + sp) * (long)(CP * CD) + r];
    g_kv[idx] = s;
}

// ---------------- pk.sum over S ----------------
__global__ void pksum_part_kernel(void)   // grid (CB, PKCH), block 128
{
    int b = blockIdx.x, ch = blockIdx.y, t = threadIdx.x;
    const int chunk = CS / PKCH;
    float acc = 0.f;
    const float* p = g_pk + ((long)b * CS + (long)ch * chunk) * CP + t;
    for (int s = 0; s < chunk; s++) acc += p[(long)s * CP];
    g_pkp[((long)ch * CB + b) * CP + t] = acc;
}

__global__ void pksum_reduce_kernel(void)
{
    int idx = blockIdx.x * blockDim.x + threadIdx.x;
    if (idx >= CB * CP) return;
    float s = 0.f;
    #pragma unroll
    for (int ch = 0; ch < PKCH; ch++)
        s += g_pkp[(long)ch * CB * CP + idx];
    g_pks[idx] = s;
}

// ---------------- z = pq . pksum (per row) ----------------
__global__ void z_kernel(void)   // grid CBS/8, block 256 (8 warps)
{
    const long row  = (long)blockIdx.x * 8 + (threadIdx.x >> 5);
    const int  lane = threadIdx.x & 31;
    const int  b    = (int)(row / CS);
    const float* pr = g_pq  + row * CP;
    const float* ps = g_pks + (long)b * CP;
    float acc = 0.f;
    #pragma unroll
    for (int i = lane; i < CP; i += 32) acc += pr[i] * ps[i];
    #pragma unroll
    for (int o = 16; o; o >>= 1) acc += __shfl_xor_sync(0xffffffffu, acc, o);
    if (lane == 0) g_z[row] = acc;
}

// ---------------- layernorm, in-place, one 128-thread block per row ----------------
__global__ void ln_kernel(float* __restrict__ X,
                          const float* __restrict__ gamma,
                          const float* __restrict__ beta)
{
    __shared__ float red[128];
    const long row = blockIdx.x;
    float4* xp = (float4*)(X + row * CD);
    const int t = threadIdx.x;
    float4 v = xp[t];

    red[t] = v.x + v.y + v.z + v.w;
    __syncthreads();
    for (int o = 64; o; o >>= 1) { if (t < o) red[t] += red[t + o]; __syncthreads(); }
    const float mu = red[0] * (1.f / CD);
    __syncthreads();

    float dx = v.x - mu, dy = v.y - mu, dz = v.z - mu, dw = v.w - mu;
    red[t] = dx*dx + dy*dy + dz*dz + dw*dw;
    __syncthreads();
    for (int o = 64; o; o >>= 1) { if (t < o) red[t] += red[t + o]; __syncthreads(); }
    const float rstd = rsqrtf(red[0] * (1.f / CD) + 1e-5f);

    const float4 g4 = ((const float4*)gamma)[t];
    const float4 b4 = ((const float4*)beta)[t];
    float4 o;
    o.x = dx * rstd * g4.x + b4.x;
    o.y = dy * rstd * g4.y + b4.y;
    o.z = dz * rstd * g4.z + b4.z;
    o.w = dw * rstd * g4.w + b4.w;
    xp[t] = o;
}

// ---------------- mean pool over S ----------------
__global__ void pool_part_kernel(void)    // grid (CB, POOLCH), block CD
{
    int b = blockIdx.x, ch = blockIdx.y, d = threadIdx.x;
    const int chunk = CS / POOLCH;
    float acc = 0.f;
    const float* p = g_h + ((long)b * CS + (long)ch * chunk) * CD + d;
    for (int s = 0; s < chunk; s++) acc += p[(long)s * CD];
    g_poolp[((long)ch * CB + b) * CD + d] = acc;
}

__global__ void pool_reduce_kernel(void)
{
    int idx = blockIdx.x * blockDim.x + threadIdx.x;
    if (idx >= CB * CD) return;
    float s = 0.f;
    #pragma unroll
    for (int ch = 0; ch < POOLCH; ch++)
        s += g_poolp[(long)ch * CB * CD + idx];
    g_pool[idx] = s * (1.f / CS);
}

// ---------------- head ----------------
__global__ void head1_kernel(const float* __restrict__ Wh1,
                             const float* __restrict__ bh1)
{
    int b = blockIdx.x, t = threadIdx.x;       // block = CDH threads
    const float* pr = g_pool + (long)b * CD;
    float acc = 0.f;
    for (int k = 0; k < CD; k++)
        acc = fmaf(pr[k], Wh1[(long)k * CDH + t], acc);
    float v = acc + bh1[t];
    g_h1[(long)b * CDH + t] = v > 0.f ? v : 0.f;
}

__global__ void head2_kernel(const float* __restrict__ Wh2,
                             const float* __restrict__ bh2,
                             float* __restrict__ out)
{
    int idx = threadIdx.x;
    if (idx >= CB * CC) return;
    int b = idx / CC, c = idx % CC;
    const float* h1 = g_h1 + (long)b * CDH;
    float acc = 0.f;
    for (int k = 0; k < CDH; k++)
        acc = fmaf(h1[k], Wh2[(long)k * CC + c], acc);
    out[idx] = acc + bh2[c];
}

// ---------------- host ----------------
extern "C" void kernel_launch(void* const* d_in, const int* in_sizes, int n_in,
                              void* d_out, int out_size)
{
    (void)in_sizes; (void)n_in; (void)out_size;

    const int*   x    = (const int*)  d_in[0];
    const float* emb  = (const float*)d_in[1];
    const float* pos  = (const float*)d_in[2];
    const float* Wq   = (const float*)d_in[3];
    const float* bq   = (const float*)d_in[4];
    const float* Wk   = (const float*)d_in[5];
    const float* bk   = (const float*)d_in[6];
    const float* Wv   = (const float*)d_in[7];
    const float* bv   = (const float*)d_in[8];
    const float* Wf   = (const float*)d_in[9];
    const float* bf   = (const float*)d_in[10];
    const float* Wo   = (const float*)d_in[11];
    const float* bo   = (const float*)d_in[12];
    const float* lng  = (const float*)d_in[13];
    const float* lnb  = (const float*)d_in[14];
    const float* W1   = (const float*)d_in[15];
    const float* b1   = (const float*)d_in[16];
    const float* W2   = (const float*)d_in[17];
    const float* b2   = (const float*)d_in[18];
    const float* Wh1  = (const float*)d_in[19];
    const float* bh1  = (const float*)d_in[20];
    const float* Wh2  = (const float*)d_in[21];
    const float* bh2  = (const float*)d_in[22];
    float* out = (float*)d_out;

    float *ph, *pq, *pk, *pv, *pa, *ppq, *ppk, *pmlp, *pkv, *pz;
    cudaGetSymbolAddress((void**)&ph,   g_h);
    cudaGetSymbolAddress((void**)&pq,   g_q);
    cudaGetSymbolAddress((void**)&pk,   g_k);
    cudaGetSymbolAddress((void**)&pv,   g_v);
    cudaGetSymbolAddress((void**)&pa,   g_a);
    cudaGetSymbolAddress((void**)&ppq,  g_pq);
    cudaGetSymbolAddress((void**)&ppk,  g_pk);
    cudaGetSymbolAddress((void**)&pmlp, g_mlp);
    cudaGetSymbolAddress((void**)&pkv,  g_kv);
    cudaGetSymbolAddress((void**)&pz,   g_z);

    embed_kernel<<<CBS, 128>>>(x, emb, pos);

    for (int l = 0; l < CL; l++) {
        const float* wq = Wq + (long)l * CD * CD;
        const float* wk = Wk + (long)l * CD * CD;
        const float* wv = Wv + (long)l * CD * CD;
        const float* wf = Wf + (long)l * CD * CP;
        const float* wo = Wo + (long)l * CD * CD;
        const float* w1 = W1 + (long)l * CD * CDF;
        const float* w2 = W2 + (long)l * CDF * CD;
        const float* biq = bq + (long)l * CD;
        const float* bik = bk + (long)l * CD;
        const float* biv = bv + (long)l * CD;
        const float* bif = bf + (long)l * CP;
        const float* bio = bo + (long)l * CD;
        const float* bi1 = b1 + (long)l * CDF;
        const float* bi2 = b2 + (long)l * CD;

        dim3 gQKV(CD / 128, CBS / 128, 1);
        sgemm_nn<0><<<gQKV, 256>>>(ph, wq, biq, pq, CBS, CD, CD, 0, 0, 0, nullptr);
        sgemm_nn<0><<<gQKV, 256>>>(ph, wk, bik, pk, CBS, CD, CD, 0, 0, 0, nullptr);
        sgemm_nn<0><<<gQKV, 256>>>(ph, wv, biv, pv, CBS, CD, CD, 0, 0, 0, nullptr);

        dim3 gF(CP / 128, CBS / 128, 1);
        sgemm_nn<1><<<gF, 256>>>(pq, wf, bif, ppq, CBS, CP, CD, 0, 0, 0, nullptr);
        sgemm_nn<1><<<gF, 256>>>(pk, wf, bif, ppk, CBS, CP, CD, 0, 0, 0, nullptr);

        pksum_part_kernel<<<dim3(CB, PKCH), 128>>>();
        pksum_reduce_kernel<<<(CB * CP + 255) / 256, 256>>>();

        sgemm_tn_split<<<dim3(CD / 128, 1, CB * KVSPLIT), 256>>>();
        kv_reduce_kernel<<<(CB * CP * CD + 255) / 256, 256>>>();

        z_kernel<<<CBS / 8, 256>>>();

        // out[b,s,d] = (pq @ kv) / (z + eps)   (batched)
        dim3 gO(CD / 128, CS / 128, CB);
        sgemm_nn<3><<<gO, 256>>>(ppq, pkv, nullptr, pa,
                                 CS, CD, CP,
                                 (long)CS * CP, (long)CP * CD, (long)CS * CD, pz);

        sgemm_nn<0><<<gQKV, 256>>>(pa, wo, bio, pq, CBS, CD, CD, 0, 0, 0, nullptr);

        ln_kernel<<<CBS, 128>>>(pq, lng + (long)l * CD, lnb + (long)l * CD);

        dim3 g1(CDF / 128, CBS / 128, 1);
        sgemm_nn<2><<<g1, 256>>>(pq, w1, bi1, pmlp, CBS, CDF, CD, 0, 0, 0, nullptr);

        dim3 g2(CD / 128, CBS / 128, 1);
        sgemm_nn<0><<<g2, 256>>>(pmlp, w2, bi2, ph, CBS, CD, CDF, 0, 0, 0, nullptr);
    }

    pool_part_kernel<<<dim3(CB, POOLCH), CD>>>();
    pool_reduce_kernel<<<(CB * CD + 255) / 256, 256>>>();
    head1_kernel<<<CB, CDH>>>(Wh1, bh1);
    head2_kernel<<<1, 32>>>(Wh2, bh2, out);
}